// round 5
// baseline (speedup 1.0000x reference)
#include <cuda_runtime.h>

// ---------------------------------------------------------------------------
// CausalTrajectoryPrediction: 64 per-node MLPs, B=1024, H=512, M=64, N=64.
//   h1 = relu(x_masked @ W1^T)            (per node: 1024x64 @ 64x512)
//   r1 = relu(h1 @ W2^T)                  (1024x512 @ 512x64)
//   h3 = relu(r1 @ W3[:, :64]^T + x_own * W3[:, 64+n] + b3)
//   out = relu(h3 @ W4 + b4)
// One CTA per (node n, 128-row batch tile). Fully fused in shared memory.
// fp32 throughout; packed fma.rn.f32x2 (Blackwell) for 2x FMA issue density.
// ---------------------------------------------------------------------------

#define THREADS 256

typedef unsigned long long ull;

__device__ __forceinline__ ull pk2(float lo, float hi) {
    ull r;
    asm("mov.b64 %0, {%1, %2};" : "=l"(r) : "f"(lo), "f"(hi));
    return r;
}
__device__ __forceinline__ float2 upk2(ull v) {
    float2 r;
    asm("mov.b64 {%0, %1}, %2;" : "=f"(r.x), "=f"(r.y) : "l"(v));
    return r;
}
__device__ __forceinline__ void fma2(ull& d, ull a, ull b) {
    asm("fma.rn.f32x2 %0, %1, %2, %0;" : "+l"(d) : "l"(a), "l"(b));
}

// Stage a 64x64 weight tile TRANSPOSED into smem, with an XOR swizzle so the
// GEMM's float4 reads are 16B-aligned and bank-conflict-free.
// Logical element (k, c) -> W[k*64 + ((((c>>2) ^ (k>>2)) & 15) << 2) + (c & 3)]
// src layout: 64 rows (one per logical column c), contiguous along k:
//   src[c * rowstride + k],  k = 0..63.
__device__ __forceinline__ void load_tile(float* __restrict__ W,
                                          const float* __restrict__ src,
                                          int rowstride) {
    int f  = threadIdx.x & 15;   // k-group: k = 4f + j, and swizzle s(k) = f
    int c0 = threadIdx.x >> 4;   // 0..15
#pragma unroll
    for (int p = 0; p < 4; ++p) {
        int c = c0 + p * 16;     // 0..63
        float4 v = *(const float4*)(src + (size_t)c * rowstride + f * 4);
        int g = ((c >> 2) ^ f) & 15;
        int base = (f * 4) * 64 + (g << 2) + (c & 3);
        W[base      ] = v.x;     // k = 4f
        W[base +  64] = v.y;     // k = 4f+1
        W[base + 128] = v.z;     // k = 4f+2
        W[base + 192] = v.w;     // k = 4f+3
    }
}

// 128x64x64 GEMM microkernel, accumulate into packed f32x2 acc[4][4]
// (4 rows x 8 cols per thread). A: row-major, 65-float row stride.
// W: swizzled tile from load_tile. rt in 0..31 (row group), ct in 0..7 (cols).
__device__ __forceinline__ void gemm64(ull acc[4][4],
                                       const float* __restrict__ A,
                                       const float* __restrict__ W,
                                       int rt, int ct) {
    const float* Arow = A + rt * 4 * 65;
#pragma unroll 4
    for (int k = 0; k < 64; ++k) {
        int s  = k >> 2;
        int g0 = ((2 * ct) ^ s) & 15;        // logical col group 2*ct
        int g1 = g0 ^ 1;                     // logical col group 2*ct+1
        ulonglong2 b01 = *(const ulonglong2*)(W + k * 64 + (g0 << 2));
        ulonglong2 b23 = *(const ulonglong2*)(W + k * 64 + (g1 << 2));
#pragma unroll
        for (int i = 0; i < 4; ++i) {
            float a = Arow[i * 65 + k];
            ull a2 = pk2(a, a);
            fma2(acc[i][0], a2, b01.x);
            fma2(acc[i][1], a2, b01.y);
            fma2(acc[i][2], a2, b23.x);
            fma2(acc[i][3], a2, b23.y);
        }
    }
}

__global__ void __launch_bounds__(THREADS, 2)
ctp_kernel(const float* __restrict__ x,  const float* __restrict__ W1,
           const float* __restrict__ W2, const float* __restrict__ W3,
           const float* __restrict__ b3, const float* __restrict__ W4,
           const float* __restrict__ b4, float* __restrict__ out) {
    extern __shared__ float sm[];
    float* Asm = sm;               // 128 x 65  = 8320 floats (x tile, later r1)
    float* Hsm = Asm + 8320;       // 128 x 65  = 8320 floats (h1 chunk)
    float* Wsm = Hsm + 8320;       //  64 x 64  = 4096 floats (swizzled W tile)
    float* W4s = Wsm + 4096;       // 512 floats
    float* w3o = W4s + 512;        //  64 floats (W3 own-input column, chunk)
    float* b3s = w3o + 64;         //  64 floats (b3 chunk)
    float* xow = b3s + 64;         // 128 floats (x[:, n] for this row tile)

    const int n       = blockIdx.y;       // node 0..63
    const int rowbase = blockIdx.x * 128; // batch row tile
    const int tid     = threadIdx.x;
    const int rt      = tid >> 3;         // 0..31 -> rows rt*4 .. rt*4+3
    const int ct      = tid & 7;          // 0..7  -> cols ct*8 .. ct*8+7

    const float* W1n = W1 + (size_t)n * 512 * 64;
    const float* W2n = W2 + (size_t)n * 64 * 512;
    const float* W3n = W3 + (size_t)n * 512 * 128;

    // ---- Stage x tile (column n masked to 0), x_own, W4 ----
    {
        int f  = tid & 15;
        int r0 = tid >> 4;
#pragma unroll
        for (int p = 0; p < 8; ++p) {
            int row = r0 + p * 16;
            float4 v = *(const float4*)(x + (size_t)(rowbase + row) * 64 + f * 4);
            float vv[4] = {v.x, v.y, v.z, v.w};
#pragma unroll
            for (int j = 0; j < 4; ++j)
                Asm[row * 65 + f * 4 + j] = (f * 4 + j == n) ? 0.0f : vv[j];
        }
    }
    for (int i = tid; i < 512; i += THREADS) W4s[i] = W4[(size_t)n * 512 + i];
    if (tid < 128) xow[tid] = x[(size_t)(rowbase + tid) * 64 + n];

    // ---- Phase B: r1 = relu( relu(A @ W1^T) @ W2^T ), chunked over H ----
    ull r1acc[4][4];
#pragma unroll
    for (int i = 0; i < 4; ++i)
#pragma unroll
        for (int q = 0; q < 4; ++q) r1acc[i][q] = 0ull;  // {0.f, 0.f}

    for (int hc = 0; hc < 8; ++hc) {
        load_tile(Wsm, W1n + (size_t)hc * 64 * 64, 64);
        __syncthreads();                       // Wsm(W1) + Asm ready

        ull acc[4][4];
#pragma unroll
        for (int i = 0; i < 4; ++i)
#pragma unroll
            for (int q = 0; q < 4; ++q) acc[i][q] = 0ull;
        gemm64(acc, Asm, Wsm, rt, ct);

        // relu(h1 chunk) -> Hsm
#pragma unroll
        for (int i = 0; i < 4; ++i) {
            int row = rt * 4 + i;
#pragma unroll
            for (int q = 0; q < 4; ++q) {
                float2 v = upk2(acc[i][q]);
                Hsm[row * 65 + ct * 8 + q * 2 + 0] = fmaxf(v.x, 0.0f);
                Hsm[row * 65 + ct * 8 + q * 2 + 1] = fmaxf(v.y, 0.0f);
            }
        }
        __syncthreads();                       // Hsm ready; Wsm(W1) drained

        load_tile(Wsm, W2n + (size_t)hc * 64, 512);
        __syncthreads();                       // Wsm(W2) ready

        gemm64(r1acc, Hsm, Wsm, rt, ct);
        __syncthreads();                       // Wsm/Hsm drained before reuse
    }

    // r1 = relu(r1acc), overlaid into the (no longer needed) Asm buffer
#pragma unroll
    for (int i = 0; i < 4; ++i) {
        int row = rt * 4 + i;
#pragma unroll
        for (int q = 0; q < 4; ++q) {
            float2 v = upk2(r1acc[i][q]);
            Asm[row * 65 + ct * 8 + q * 2 + 0] = fmaxf(v.x, 0.0f);
            Asm[row * 65 + ct * 8 + q * 2 + 1] = fmaxf(v.y, 0.0f);
        }
    }

    // ---- Phase C: out = relu( relu(R @ W3a^T + x_own*w3own + b3) @ W4 + b4 )
    float partial[4] = {0.0f, 0.0f, 0.0f, 0.0f};
    const float b4n = b4[n];

    for (int hc = 0; hc < 8; ++hc) {
        load_tile(Wsm, W3n + (size_t)hc * 64 * 128, 128);
        if (tid < 64) {
            int h = hc * 64 + tid;
            w3o[tid] = W3n[(size_t)h * 128 + 64 + n];
            b3s[tid] = b3[(size_t)n * 512 + h];
        }
        __syncthreads();                       // Wsm(W3), w3o, b3s, R ready

        ull acc[4][4];
        float xo[4];
#pragma unroll
        for (int i = 0; i < 4; ++i) xo[i] = xow[rt * 4 + i];
#pragma unroll
        for (int q = 0; q < 4; ++q) {
            int c = ct * 8 + q * 2;
            float w0 = w3o[c], w1 = w3o[c + 1];
            float c0 = b3s[c], c1 = b3s[c + 1];
#pragma unroll
            for (int i = 0; i < 4; ++i)
                acc[i][q] = pk2(fmaf(xo[i], w0, c0), fmaf(xo[i], w1, c1));
        }
        gemm64(acc, Asm, Wsm, rt, ct);

        // relu(h3 chunk), fold directly into the W4 dot product
#pragma unroll
        for (int i = 0; i < 4; ++i) {
#pragma unroll
            for (int q = 0; q < 4; ++q) {
                float2 v = upk2(acc[i][q]);
                int c = hc * 64 + ct * 8 + q * 2;
                partial[i] = fmaf(fmaxf(v.x, 0.0f), W4s[c],     partial[i]);
                partial[i] = fmaf(fmaxf(v.y, 0.0f), W4s[c + 1], partial[i]);
            }
        }
        __syncthreads();                       // Wsm/w3o/b3s drained
    }

    // ---- Reduce partial over the 8 ct lanes (same-warp, lanes l, l^1, l^2, l^4)
#pragma unroll
    for (int i = 0; i < 4; ++i) {
        float v = partial[i];
        v += __shfl_xor_sync(0xffffffffu, v, 1);
        v += __shfl_xor_sync(0xffffffffu, v, 2);
        v += __shfl_xor_sync(0xffffffffu, v, 4);
        if (ct == 0)
            out[(size_t)(rowbase + rt * 4 + i) * 64 + n] = fmaxf(v + b4n, 0.0f);
    }
}

extern "C" void kernel_launch(void* const* d_in, const int* in_sizes, int n_in,
                              void* d_out, int out_size) {
    const float* x  = (const float*)d_in[0];
    const float* W1 = (const float*)d_in[1];
    const float* W2 = (const float*)d_in[2];
    const float* W3 = (const float*)d_in[3];
    const float* b3 = (const float*)d_in[4];
    const float* W4 = (const float*)d_in[5];
    const float* b4 = (const float*)d_in[6];
    float* out = (float*)d_out;

    const int smem_bytes = 21504 * (int)sizeof(float);  // 86016 B
    cudaFuncSetAttribute(ctp_kernel,
                         cudaFuncAttributeMaxDynamicSharedMemorySize,
                         smem_bytes);

    dim3 grid(8, 64);   // 8 row tiles of 128 x 64 nodes
    ctp_kernel<<<grid, THREADS, smem_bytes>>>(x, W1, W2, W3, b3, W4, b4, out);
}